// round 1
// baseline (speedup 1.0000x reference)
#include <cuda_runtime.h>
#include <cuda_bf16.h>

#define DIM   1024
#define NQ    512
#define NKV   2048
#define NCTX  2560
#define BATCH 4
#define HEADS 16
#define DH    64

// ---------------- scratch (no allocs allowed) ----------------
__device__ float g_kvn[(long)BATCH * NCTX * DIM];   // LN(kv) rows 0..2047, LN(q) rows 2048..2559 per batch
__device__ float g_q  [(long)BATCH * NQ   * DIM];
__device__ float g_k  [(long)BATCH * NCTX * DIM];
__device__ float g_v  [(long)BATCH * NCTX * DIM];
__device__ float g_att[(long)BATCH * NQ   * DIM];

// ---------------- LayerNorm ----------------
__global__ __launch_bounds__(256)
void ln_kernel(const float* __restrict__ x, float* __restrict__ y,
               const float* __restrict__ g, const float* __restrict__ bb,
               int rows_per_batch, int out_batch_stride, int out_row_off)
{
    __shared__ float red[8];
    __shared__ float s_mu, s_rstd;
    long row = blockIdx.x;
    int b = (int)(row / rows_per_batch);
    int r = (int)(row - (long)b * rows_per_batch);
    const float* xr = x + row * (long)DIM;
    float* yr = y + ((long)b * out_batch_stride + out_row_off + r) * (long)DIM;
    int tid = threadIdx.x;

    float4 v = *(const float4*)(xr + tid * 4);
    float s = v.x + v.y + v.z + v.w;
    #pragma unroll
    for (int o = 16; o > 0; o >>= 1) s += __shfl_xor_sync(0xffffffffu, s, o);
    if ((tid & 31) == 0) red[tid >> 5] = s;
    __syncthreads();
    if (tid == 0) {
        float t = 0.f;
        #pragma unroll
        for (int i = 0; i < 8; i++) t += red[i];
        s_mu = t * (1.f / DIM);
    }
    __syncthreads();
    float mu = s_mu;
    float d0 = v.x - mu, d1 = v.y - mu, d2 = v.z - mu, d3 = v.w - mu;
    float q = d0*d0 + d1*d1 + d2*d2 + d3*d3;
    #pragma unroll
    for (int o = 16; o > 0; o >>= 1) q += __shfl_xor_sync(0xffffffffu, q, o);
    if ((tid & 31) == 0) red[tid >> 5] = q;
    __syncthreads();
    if (tid == 0) {
        float t = 0.f;
        #pragma unroll
        for (int i = 0; i < 8; i++) t += red[i];
        s_rstd = rsqrtf(t * (1.f / DIM) + 1e-5f);
    }
    __syncthreads();
    float rstd = s_rstd;
    float4 gg = *(const float4*)(g  + tid * 4);
    float4 b4 = *(const float4*)(bb + tid * 4);
    float4 o4;
    o4.x = d0 * rstd * gg.x + b4.x;
    o4.y = d1 * rstd * gg.y + b4.y;
    o4.z = d2 * rstd * gg.z + b4.z;
    o4.w = d3 * rstd * gg.w + b4.w;
    *(float4*)(yr + tid * 4) = o4;
}

// ---------------- SGEMM: C = A(MxK) @ B(KxN) + bias (+resid) ----------------
// 128x128 tile, BK=8, 256 threads, 8x8 microtile
__global__ __launch_bounds__(256)
void sgemm_kernel(const float* __restrict__ A, const float* __restrict__ B,
                  const float* __restrict__ bias, const float* __restrict__ resid,
                  float* __restrict__ C, int N, int K,
                  long strideA, long strideC)
{
    __shared__ float As[8][128];
    __shared__ float Bs[8][128];
    const int tid = threadIdx.x;
    const float* Ab = A + (long)blockIdx.z * strideA + (long)blockIdx.y * 128 * K;
    const float* Bb = B + blockIdx.x * 128;
    const long coff = (long)blockIdx.z * strideC + (long)blockIdx.y * 128 * N + blockIdx.x * 128;
    float* Cb = C + coff;

    const int aRow = tid >> 1, aCol = (tid & 1) << 2;
    const int bRow = tid >> 5, bCol = (tid & 31) << 2;
    const int tx = tid & 15, ty = tid >> 4;

    float acc[8][8];
    #pragma unroll
    for (int i = 0; i < 8; i++)
        #pragma unroll
        for (int j = 0; j < 8; j++) acc[i][j] = 0.f;

    for (int k0 = 0; k0 < K; k0 += 8) {
        float4 a4 = *(const float4*)(Ab + (long)aRow * K + k0 + aCol);
        As[aCol + 0][aRow] = a4.x;
        As[aCol + 1][aRow] = a4.y;
        As[aCol + 2][aRow] = a4.z;
        As[aCol + 3][aRow] = a4.w;
        *(float4*)(&Bs[bRow][bCol]) = *(const float4*)(Bb + (long)(k0 + bRow) * N + bCol);
        __syncthreads();
        #pragma unroll
        for (int k = 0; k < 8; k++) {
            float ra[8], rb[8];
            #pragma unroll
            for (int i = 0; i < 8; i++) ra[i] = As[k][ty * 8 + i];
            #pragma unroll
            for (int j = 0; j < 8; j++) rb[j] = Bs[k][tx * 8 + j];
            #pragma unroll
            for (int i = 0; i < 8; i++)
                #pragma unroll
                for (int j = 0; j < 8; j++)
                    acc[i][j] = fmaf(ra[i], rb[j], acc[i][j]);
        }
        __syncthreads();
    }

    const float* Rb = resid ? (resid + coff) : nullptr;
    #pragma unroll
    for (int i = 0; i < 8; i++) {
        int r = ty * 8 + i;
        #pragma unroll
        for (int j = 0; j < 8; j += 4) {
            int c = tx * 8 + j;
            float4 o;
            o.x = acc[i][j + 0] + bias[blockIdx.x * 128 + c + 0];
            o.y = acc[i][j + 1] + bias[blockIdx.x * 128 + c + 1];
            o.z = acc[i][j + 2] + bias[blockIdx.x * 128 + c + 2];
            o.w = acc[i][j + 3] + bias[blockIdx.x * 128 + c + 3];
            if (Rb) {
                float4 rr = *(const float4*)(Rb + (long)r * N + c);
                o.x += rr.x; o.y += rr.y; o.z += rr.z; o.w += rr.w;
            }
            *(float4*)(Cb + (long)r * N + c) = o;
        }
    }
}

// ---------------- Flash attention (64q x 64k tiles, online softmax) ----------------
#define TQ 64
#define TK 64
#define LDT 68
#define ATTN_SMEM ((4 * 64 * LDT + 3 * 64) * 4)

__global__ __launch_bounds__(256)
void attn_kernel(const float* __restrict__ Q, const float* __restrict__ K,
                 const float* __restrict__ V, float* __restrict__ O)
{
    extern __shared__ float sm[];
    float* Qt   = sm;                 // [DH][TQ] stride LDT (transposed)
    float* Kt   = Qt + 64 * LDT;      // [DH][TK] (transposed)
    float* Vs   = Kt + 64 * LDT;      // [TK][DH] stride LDT
    float* Ss   = Vs + 64 * LDT;      // [TQ][TK] stride LDT
    float* mrow = Ss + 64 * LDT;      // [TQ]
    float* lrow = mrow + TQ;          // [TQ]
    float* arow = lrow + TQ;          // [TQ]

    const int qt = blockIdx.x, h = blockIdx.y, b = blockIdx.z;
    const int tid = threadIdx.x;
    const int tx = tid & 15, ty = tid >> 4;
    const float scale = 0.125f; // 64^-0.5

    // load Q tile transposed + pre-scaled
    {
        int r  = tid >> 2;
        int c0 = (tid & 3) << 4;
        const float* src = Q + ((long)(b * NQ + qt * TQ + r)) * DIM + h * DH + c0;
        #pragma unroll
        for (int c = 0; c < 16; c += 4) {
            float4 v4 = *(const float4*)(src + c);
            Qt[(c0 + c + 0) * LDT + r] = v4.x * scale;
            Qt[(c0 + c + 1) * LDT + r] = v4.y * scale;
            Qt[(c0 + c + 2) * LDT + r] = v4.z * scale;
            Qt[(c0 + c + 3) * LDT + r] = v4.w * scale;
        }
    }
    if (tid < TQ) { mrow[tid] = -1e30f; lrow[tid] = 0.f; }

    float acc[4][4];
    #pragma unroll
    for (int i = 0; i < 4; i++)
        #pragma unroll
        for (int j = 0; j < 4; j++) acc[i][j] = 0.f;

    for (int j0 = 0; j0 < NCTX; j0 += TK) {
        __syncthreads();  // protect prior-iter reads of Kt/Vs/Ss; covers Q load first iter
        {
            int r  = tid >> 2;
            int c0 = (tid & 3) << 4;
            const float* ksrc = K + ((long)(b * NCTX + j0 + r)) * DIM + h * DH + c0;
            const float* vsrc = V + ((long)(b * NCTX + j0 + r)) * DIM + h * DH + c0;
            #pragma unroll
            for (int c = 0; c < 16; c += 4) {
                float4 k4 = *(const float4*)(ksrc + c);
                Kt[(c0 + c + 0) * LDT + r] = k4.x;
                Kt[(c0 + c + 1) * LDT + r] = k4.y;
                Kt[(c0 + c + 2) * LDT + r] = k4.z;
                Kt[(c0 + c + 3) * LDT + r] = k4.w;
                *(float4*)(Vs + r * LDT + c0 + c) = *(const float4*)(vsrc + c);
            }
        }
        __syncthreads();

        // S = (Q*scale) @ K^T   (4x4 microtile per thread, conflict-free LDS.128)
        float s[4][4];
        #pragma unroll
        for (int i = 0; i < 4; i++)
            #pragma unroll
            for (int j = 0; j < 4; j++) s[i][j] = 0.f;
        #pragma unroll 8
        for (int d = 0; d < DH; d++) {
            float4 qa = *(const float4*)(Qt + d * LDT + ty * 4);
            float4 kb = *(const float4*)(Kt + d * LDT + tx * 4);
            float qv[4] = {qa.x, qa.y, qa.z, qa.w};
            float kv[4] = {kb.x, kb.y, kb.z, kb.w};
            #pragma unroll
            for (int i = 0; i < 4; i++)
                #pragma unroll
                for (int j = 0; j < 4; j++)
                    s[i][j] = fmaf(qv[i], kv[j], s[i][j]);
        }
        #pragma unroll
        for (int i = 0; i < 4; i++)
            *(float4*)(Ss + (ty * 4 + i) * LDT + tx * 4) =
                make_float4(s[i][0], s[i][1], s[i][2], s[i][3]);
        __syncthreads();

        // per-row max / alpha (64 stat threads)
        if (tid < TQ) {
            float m_old = mrow[tid];
            float mt = m_old;
            const float* srow = Ss + tid * LDT;
            #pragma unroll 8
            for (int j = 0; j < TK; j++) mt = fmaxf(mt, srow[j]);
            float alpha = __expf(m_old - mt);
            mrow[tid] = mt;
            arow[tid] = alpha;
            lrow[tid] *= alpha;
        }
        __syncthreads();

        // P = exp(S - m_new), rescale acc, write P to Ss
        float mn[4], al[4];
        #pragma unroll
        for (int i = 0; i < 4; i++) { mn[i] = mrow[ty * 4 + i]; al[i] = arow[ty * 4 + i]; }
        #pragma unroll
        for (int i = 0; i < 4; i++) {
            float p0 = __expf(s[i][0] - mn[i]);
            float p1 = __expf(s[i][1] - mn[i]);
            float p2 = __expf(s[i][2] - mn[i]);
            float p3 = __expf(s[i][3] - mn[i]);
            *(float4*)(Ss + (ty * 4 + i) * LDT + tx * 4) = make_float4(p0, p1, p2, p3);
            #pragma unroll
            for (int j = 0; j < 4; j++) acc[i][j] *= al[i];
        }
        __syncthreads();

        // l update (64 stat threads) — runs concurrent with AV (both read-only on Ss)
        if (tid < TQ) {
            float sum = 0.f;
            const float* srow = Ss + tid * LDT;
            #pragma unroll 8
            for (int j = 0; j < TK; j++) sum += srow[j];
            lrow[tid] += sum;
        }

        // acc += P @ V
        #pragma unroll 4
        for (int j = 0; j < TK; j++) {
            float pv[4];
            #pragma unroll
            for (int i = 0; i < 4; i++) pv[i] = Ss[(ty * 4 + i) * LDT + j];
            float4 vv = *(const float4*)(Vs + j * LDT + tx * 4);
            float vr[4] = {vv.x, vv.y, vv.z, vv.w};
            #pragma unroll
            for (int i = 0; i < 4; i++)
                #pragma unroll
                for (int dd = 0; dd < 4; dd++)
                    acc[i][dd] = fmaf(pv[i], vr[dd], acc[i][dd]);
        }
    }
    __syncthreads();  // lrow final

    #pragma unroll
    for (int i = 0; i < 4; i++) {
        float linv = 1.f / lrow[ty * 4 + i];
        float4 o4 = make_float4(acc[i][0] * linv, acc[i][1] * linv,
                                acc[i][2] * linv, acc[i][3] * linv);
        *(float4*)(O + ((long)(b * NQ + qt * TQ + ty * 4 + i)) * DIM + h * DH + tx * 4) = o4;
    }
}

// ---------------- launch ----------------
extern "C" void kernel_launch(void* const* d_in, const int* in_sizes, int n_in,
                              void* d_out, int out_size)
{
    const float* query   = (const float*)d_in[0];
    const float* kv      = (const float*)d_in[1];
    const float* ln_q_g  = (const float*)d_in[2];
    const float* ln_q_b  = (const float*)d_in[3];
    const float* ln_kv_g = (const float*)d_in[4];
    const float* ln_kv_b = (const float*)d_in[5];
    const float* Wq = (const float*)d_in[6];
    const float* bq = (const float*)d_in[7];
    const float* Wk = (const float*)d_in[8];
    const float* bk = (const float*)d_in[9];
    const float* Wv = (const float*)d_in[10];
    const float* bv = (const float*)d_in[11];
    const float* Wo = (const float*)d_in[12];
    const float* bo = (const float*)d_in[13];
    float* out = (float*)d_out;

    float *kvn, *qb, *kb, *vb, *ab;
    cudaGetSymbolAddress((void**)&kvn, g_kvn);
    cudaGetSymbolAddress((void**)&qb,  g_q);
    cudaGetSymbolAddress((void**)&kb,  g_k);
    cudaGetSymbolAddress((void**)&vb,  g_v);
    cudaGetSymbolAddress((void**)&ab,  g_att);

    // LayerNorms: kv_n -> rows [0,2048), q_n -> rows [2048,2560) per batch of g_kvn
    ln_kernel<<<BATCH * NKV, 256>>>(kv,    kvn, ln_kv_g, ln_kv_b, NKV, NCTX, 0);
    ln_kernel<<<BATCH * NQ,  256>>>(query, kvn, ln_q_g,  ln_q_b,  NQ,  NCTX, NKV);

    // Q = q_n @ Wq + bq   (per-batch strided A)
    {
        dim3 grid(DIM / 128, NQ / 128, BATCH);
        sgemm_kernel<<<grid, 256>>>(kvn + (long)NKV * DIM, Wq, bq, nullptr, qb,
                                    DIM, DIM, (long)NCTX * DIM, (long)NQ * DIM);
    }
    // K, V = kv_input @ W + b   (whole buffer contiguous: 10240 rows)
    {
        dim3 grid(DIM / 128, BATCH * NCTX / 128, 1);
        sgemm_kernel<<<grid, 256>>>(kvn, Wk, bk, nullptr, kb, DIM, DIM, 0, 0);
        sgemm_kernel<<<grid, 256>>>(kvn, Wv, bv, nullptr, vb, DIM, DIM, 0, 0);
    }

    // attention
    cudaFuncSetAttribute(attn_kernel, cudaFuncAttributeMaxDynamicSharedMemorySize, ATTN_SMEM);
    {
        dim3 grid(NQ / TQ, HEADS, BATCH);
        attn_kernel<<<grid, 256, ATTN_SMEM>>>(qb, kb, vb, ab);
    }

    // out = attn @ Wo + bo + query
    {
        dim3 grid(DIM / 128, BATCH * NQ / 128, 1);
        sgemm_kernel<<<grid, 256>>>(ab, Wo, bo, query, out, DIM, DIM, 0, 0);
    }
}

// round 3
// speedup vs baseline: 2.2449x; 2.2449x over previous
#include <cuda_runtime.h>
#include <cuda_bf16.h>
#include <cstdint>

#define DIM   1024
#define NQ    512
#define NKV   2048
#define NCTX  2560
#define BATCH 4
#define HEADS 16
#define DH    64

// ---------------- scratch (no allocs allowed) ----------------
__device__ __nv_bfloat16 g_kvn[(long)BATCH * NCTX * DIM];  // LN outputs (bf16)
__device__ __nv_bfloat16 g_wt [4L * DIM * DIM];            // transposed bf16 weights [n][k]
__device__ float         g_q  [(long)BATCH * NQ   * DIM];
__device__ float         g_k  [(long)BATCH * NCTX * DIM];
__device__ float         g_v  [(long)BATCH * NCTX * DIM];
__device__ __nv_bfloat16 g_att[(long)BATCH * NQ   * DIM];  // attention output (bf16)

// ================= PTX helpers (base sm_103 features only) =================
__device__ __forceinline__ uint32_t smem_u32(const void* p) {
    uint32_t a;
    asm("{ .reg .u64 t; cvta.to.shared.u64 t, %1; cvt.u32.u64 %0, t; }" : "=r"(a) : "l"(p));
    return a;
}
__device__ __forceinline__ void cp16(uint32_t dst, const void* src) {
    asm volatile("cp.async.cg.shared.global [%0], [%1], 16;" :: "r"(dst), "l"(src));
}
__device__ __forceinline__ void cp_commit() {
    asm volatile("cp.async.commit_group;" ::: "memory");
}
template <int N>
__device__ __forceinline__ void cp_wait() {
    asm volatile("cp.async.wait_group %0;" :: "n"(N) : "memory");
}
#define LDSM_X4(r0, r1, r2, r3, addr) \
    asm volatile("ldmatrix.sync.aligned.m8n8.x4.shared.b16 {%0,%1,%2,%3}, [%4];" \
        : "=r"(r0), "=r"(r1), "=r"(r2), "=r"(r3) : "r"(addr))
#define MMA16816(d, a0, a1, a2, a3, b0, b1) \
    asm volatile("mma.sync.aligned.m16n8k16.row.col.f32.bf16.bf16.f32 " \
        "{%0,%1,%2,%3}, {%4,%5,%6,%7}, {%8,%9}, {%0,%1,%2,%3};" \
        : "+f"((d)[0]), "+f"((d)[1]), "+f"((d)[2]), "+f"((d)[3]) \
        : "r"(a0), "r"(a1), "r"(a2), "r"(a3), "r"(b0), "r"(b1))

// ---------------- LayerNorm (fp32 in, bf16 out) ----------------
__global__ __launch_bounds__(256)
void ln_kernel(const float* __restrict__ x, __nv_bfloat16* __restrict__ y,
               const float* __restrict__ g, const float* __restrict__ bb,
               int rows_per_batch, int out_batch_stride, int out_row_off)
{
    __shared__ float red[8];
    __shared__ float s_mu, s_rstd;
    long row = blockIdx.x;
    int b = (int)(row / rows_per_batch);
    int r = (int)(row - (long)b * rows_per_batch);
    const float* xr = x + row * (long)DIM;
    __nv_bfloat16* yr = y + ((long)b * out_batch_stride + out_row_off + r) * (long)DIM;
    int tid = threadIdx.x;

    float4 v = *(const float4*)(xr + tid * 4);
    float s = v.x + v.y + v.z + v.w;
    #pragma unroll
    for (int o = 16; o > 0; o >>= 1) s += __shfl_xor_sync(0xffffffffu, s, o);
    if ((tid & 31) == 0) red[tid >> 5] = s;
    __syncthreads();
    if (tid == 0) {
        float t = 0.f;
        #pragma unroll
        for (int i = 0; i < 8; i++) t += red[i];
        s_mu = t * (1.f / DIM);
    }
    __syncthreads();
    float mu = s_mu;
    float d0 = v.x - mu, d1 = v.y - mu, d2 = v.z - mu, d3 = v.w - mu;
    float q = d0*d0 + d1*d1 + d2*d2 + d3*d3;
    #pragma unroll
    for (int o = 16; o > 0; o >>= 1) q += __shfl_xor_sync(0xffffffffu, q, o);
    if ((tid & 31) == 0) red[tid >> 5] = q;
    __syncthreads();
    if (tid == 0) {
        float t = 0.f;
        #pragma unroll
        for (int i = 0; i < 8; i++) t += red[i];
        s_rstd = rsqrtf(t * (1.f / DIM) + 1e-5f);
    }
    __syncthreads();
    float rstd = s_rstd;
    float4 gg = *(const float4*)(g  + tid * 4);
    float4 b4 = *(const float4*)(bb + tid * 4);
    float o0 = d0 * rstd * gg.x + b4.x;
    float o1 = d1 * rstd * gg.y + b4.y;
    float o2 = d2 * rstd * gg.z + b4.z;
    float o3 = d3 * rstd * gg.w + b4.w;
    __nv_bfloat162 p0 = __floats2bfloat162_rn(o0, o1);
    __nv_bfloat162 p1 = __floats2bfloat162_rn(o2, o3);
    uint2 u;
    u.x = *reinterpret_cast<uint32_t*>(&p0);
    u.y = *reinterpret_cast<uint32_t*>(&p1);
    *reinterpret_cast<uint2*>(yr + tid * 4) = u;
}

// ---------------- weight transpose+convert: Wt[n][k] = bf16(W[k][n]) ----------------
__global__ __launch_bounds__(256)
void wtrans_kernel(const float* __restrict__ W, __nv_bfloat16* __restrict__ Wt)
{
    __shared__ float s[32][33];
    int tx = threadIdx.x, ty = threadIdx.y;
    int n0 = blockIdx.x * 32, k0 = blockIdx.y * 32;
    #pragma unroll
    for (int i = 0; i < 32; i += 8)
        s[ty + i][tx] = W[(long)(k0 + ty + i) * DIM + n0 + tx];
    __syncthreads();
    #pragma unroll
    for (int i = 0; i < 32; i += 8)
        Wt[(long)(n0 + ty + i) * DIM + k0 + tx] = __float2bfloat16(s[tx][ty + i]);
}

// ---------------- mma.sync bf16 GEMM: C(f32) = A(bf16 MxK) @ Bt(bf16 NxK)^T + bias (+resid)
// 128x128 tile, BK=32, 256 threads (8 warps: 2M x 4N, warp tile 64x32), 3-stage cp.async
#define GK        1024
#define NIT       32            // K / 32
#define ST        3
#define STAGE_B   16384         // A 8KB + B 8KB
#define GEMM_SMEM (ST * STAGE_B + 1024)

__global__ __launch_bounds__(256)
void gemm_bf16_kernel(const __nv_bfloat16* __restrict__ A,
                      const __nv_bfloat16* __restrict__ Bt,
                      const float* __restrict__ bias,
                      const float* __restrict__ resid,
                      float* __restrict__ C,
                      long strideA, long strideC)
{
    extern __shared__ char smraw[];
    uint32_t base = (smem_u32(smraw) + 1023u) & ~1023u;

    const int tid  = threadIdx.x;
    const int lane = tid & 31;
    const int wid  = tid >> 5;
    const int wm   = wid & 1;        // 0..1  (M)
    const int wn   = wid >> 1;       // 0..3  (N)

    const __nv_bfloat16* Ab = A + blockIdx.z * strideA + (long)blockIdx.y * 128 * GK;
    const __nv_bfloat16* Bb = Bt + (long)blockIdx.x * 128 * GK;

    // per-thread load coords: row = tid/2 (0..127), two 16B chunks at cb, cb+1
    const int lr  = tid >> 1;
    const int lcb = (tid & 1) * 2;
    const int lsw = (lr >> 1) & 3;
    const uint32_t lrowoff = lr * 64;

    auto load_stage = [&](int it) {
        uint32_t sA = base + (it % ST) * STAGE_B;
        uint32_t sB = sA + 8192;
        const __nv_bfloat16* ga = Ab + (long)lr * GK + it * 32 + lcb * 8;
        const __nv_bfloat16* gb = Bb + (long)lr * GK + it * 32 + lcb * 8;
        uint32_t o0 = lrowoff + (uint32_t)((lcb ^ lsw) << 4);
        uint32_t o1 = lrowoff + (uint32_t)(((lcb + 1) ^ lsw) << 4);
        cp16(sA + o0, ga);
        cp16(sA + o1, ga + 8);
        cp16(sB + o0, gb);
        cp16(sB + o1, gb + 8);
        cp_commit();
    };

    float acc[4][4][4];
    #pragma unroll
    for (int i = 0; i < 4; i++)
        #pragma unroll
        for (int j = 0; j < 4; j++)
            #pragma unroll
            for (int q = 0; q < 4; q++) acc[i][j][q] = 0.f;

    load_stage(0);
    load_stage(1);

    // precompute ldmatrix lane geometry
    const int a_r8 = (lane & 7) + ((lane >> 3) & 1) * 8;   // row within 16-row tile
    const int a_cq = (lane >> 4);                          // 0..1 chunk within kstep
    const int b_r8 = (lane & 7) + ((lane >> 4) & 1) * 8;
    const int b_cq = (lane >> 3) & 1;

    for (int it = 0; it < NIT; it++) {
        cp_wait<1>();
        __syncthreads();
        if (it + 2 < NIT) load_stage(it + 2);
        else cp_commit();

        uint32_t sA = base + (it % ST) * STAGE_B;
        uint32_t sB = sA + 8192;

        #pragma unroll
        for (int ks = 0; ks < 2; ks++) {
            uint32_t a[4][4];
            #pragma unroll
            for (int i = 0; i < 4; i++) {
                int r = wm * 64 + i * 16 + a_r8;
                int c = ks * 2 + a_cq;
                LDSM_X4(a[i][0], a[i][1], a[i][2], a[i][3],
                        sA + r * 64 + (((c ^ ((r >> 1) & 3))) << 4));
            }
            uint32_t b[2][4];
            #pragma unroll
            for (int jj = 0; jj < 2; jj++) {
                int r = wn * 32 + jj * 16 + b_r8;
                int c = ks * 2 + b_cq;
                LDSM_X4(b[jj][0], b[jj][1], b[jj][2], b[jj][3],
                        sB + r * 64 + (((c ^ ((r >> 1) & 3))) << 4));
            }
            #pragma unroll
            for (int i = 0; i < 4; i++)
                #pragma unroll
                for (int j = 0; j < 4; j++)
                    MMA16816(acc[i][j], a[i][0], a[i][1], a[i][2], a[i][3],
                             b[j >> 1][(j & 1) * 2], b[j >> 1][(j & 1) * 2 + 1]);
        }
    }

    // epilogue
    const long crow0 = blockIdx.z * strideC + ((long)blockIdx.y * 128 + wm * 64) * (long)DIM;
    const int  col0  = blockIdx.x * 128 + wn * 32;
    #pragma unroll
    for (int i = 0; i < 4; i++) {
        int rr = i * 16 + (lane >> 2);
        #pragma unroll
        for (int j = 0; j < 4; j++) {
            int cc = col0 + j * 8 + (lane & 3) * 2;
            float bx = bias[cc], by = bias[cc + 1];
            long off0 = crow0 + (long)(wm ? 0 : 0) + (long)rr * DIM + cc;   // rows rr
            long off1 = off0 + 8L * DIM;                                     // rows rr+8
            float2 o0, o1;
            o0.x = acc[i][j][0] + bx; o0.y = acc[i][j][1] + by;
            o1.x = acc[i][j][2] + bx; o1.y = acc[i][j][3] + by;
            if (resid) {
                float2 r0 = *(const float2*)(resid + off0);
                float2 r1 = *(const float2*)(resid + off1);
                o0.x += r0.x; o0.y += r0.y;
                o1.x += r1.x; o1.y += r1.y;
            }
            *(float2*)(C + off0) = o0;
            *(float2*)(C + off1) = o1;
        }
    }
}

// ---------------- Flash attention (fp32 FFMA, bf16 output) ----------------
#define TQ 64
#define TK 64
#define LDT 68
#define ATTN_SMEM ((4 * 64 * LDT + 3 * 64) * 4)

__global__ __launch_bounds__(256)
void attn_kernel(const float* __restrict__ Q, const float* __restrict__ K,
                 const float* __restrict__ V, __nv_bfloat16* __restrict__ O)
{
    extern __shared__ float sm[];
    float* Qt   = sm;
    float* Kt   = Qt + 64 * LDT;
    float* Vs   = Kt + 64 * LDT;
    float* Ss   = Vs + 64 * LDT;
    float* mrow = Ss + 64 * LDT;
    float* lrow = mrow + TQ;
    float* arow = lrow + TQ;

    const int qt = blockIdx.x, h = blockIdx.y, b = blockIdx.z;
    const int tid = threadIdx.x;
    const int tx = tid & 15, ty = tid >> 4;
    const float scale = 0.125f;

    {
        int r  = tid >> 2;
        int c0 = (tid & 3) << 4;
        const float* src = Q + ((long)(b * NQ + qt * TQ + r)) * DIM + h * DH + c0;
        #pragma unroll
        for (int c = 0; c < 16; c += 4) {
            float4 v4 = *(const float4*)(src + c);
            Qt[(c0 + c + 0) * LDT + r] = v4.x * scale;
            Qt[(c0 + c + 1) * LDT + r] = v4.y * scale;
            Qt[(c0 + c + 2) * LDT + r] = v4.z * scale;
            Qt[(c0 + c + 3) * LDT + r] = v4.w * scale;
        }
    }
    if (tid < TQ) { mrow[tid] = -1e30f; lrow[tid] = 0.f; }

    float acc[4][4];
    #pragma unroll
    for (int i = 0; i < 4; i++)
        #pragma unroll
        for (int j = 0; j < 4; j++) acc[i][j] = 0.f;

    for (int j0 = 0; j0 < NCTX; j0 += TK) {
        __syncthreads();
        {
            int r  = tid >> 2;
            int c0 = (tid & 3) << 4;
            const float* ksrc = K + ((long)(b * NCTX + j0 + r)) * DIM + h * DH + c0;
            const float* vsrc = V + ((long)(b * NCTX + j0 + r)) * DIM + h * DH + c0;
            #pragma unroll
            for (int c = 0; c < 16; c += 4) {
                float4 k4 = *(const float4*)(ksrc + c);
                Kt[(c0 + c + 0) * LDT + r] = k4.x;
                Kt[(c0 + c + 1) * LDT + r] = k4.y;
                Kt[(c0 + c + 2) * LDT + r] = k4.z;
                Kt[(c0 + c + 3) * LDT + r] = k4.w;
                *(float4*)(Vs + r * LDT + c0 + c) = *(const float4*)(vsrc + c);
            }
        }
        __syncthreads();

        float s[4][4];
        #pragma unroll
        for (int i = 0; i < 4; i++)
            #pragma unroll
            for (int j = 0; j < 4; j++) s[i][j] = 0.f;
        #pragma unroll 8
        for (int d = 0; d < DH; d++) {
            float4 qa = *(const float4*)(Qt + d * LDT + ty * 4);
            float4 kb = *(const float4*)(Kt + d * LDT + tx * 4);
            float qv[4] = {qa.x, qa.y, qa.z, qa.w};
            float kv[4] = {kb.x, kb.y, kb.z, kb.w};
            #pragma unroll
            for (int i = 0; i < 4; i++)
                #pragma unroll
                for (int j = 0; j < 4; j++)
                    s[i][j] = fmaf(qv[i], kv[j], s[i][j]);
        }
        #pragma unroll
        for (int i = 0; i < 4; i++)
            *(float4*)(Ss + (ty * 4 + i) * LDT + tx * 4) =
                make_float4(s[i][0], s[i][1], s[i][2], s[i][3]);
        __syncthreads();

        if (tid < TQ) {
            float m_old = mrow[tid];
            float mt = m_old;
            const float* srow = Ss + tid * LDT;
            #pragma unroll 8
            for (int j = 0; j < TK; j++) mt = fmaxf(mt, srow[j]);
            float alpha = __expf(m_old - mt);
            mrow[tid] = mt;
            arow[tid] = alpha;
            lrow[tid] *= alpha;
        }
        __syncthreads();

        float mn[4], al[4];
        #pragma unroll
        for (int i = 0; i < 4; i++) { mn[i] = mrow[ty * 4 + i]; al[i] = arow[ty * 4 + i]; }
        #pragma unroll
        for (int i = 0; i < 4; i++) {
            float p0 = __expf(s[i][0] - mn[i]);
            float p1 = __expf(s[i][1] - mn[i]);
            float p2 = __expf(s[i][2] - mn[i]);
            float p3 = __expf(s[i][3] - mn[i]);
            *(float4*)(Ss + (ty * 4 + i) * LDT + tx * 4) = make_float4(p0, p1, p2, p3);
            #pragma unroll
            for (int j = 0; j < 4; j++) acc[i][j] *= al[i];
        }
        __syncthreads();

        if (tid < TQ) {
            float sum = 0.f;
            const float* srow = Ss + tid * LDT;
            #pragma unroll 8
            for (int j = 0; j < TK; j++) sum += srow[j];
            lrow[tid] += sum;
        }

        #pragma unroll 4
        for (int j = 0; j < TK; j++) {
            float pv[4];
            #pragma unroll
            for (int i = 0; i < 4; i++) pv[i] = Ss[(ty * 4 + i) * LDT + j];
            float4 vv = *(const float4*)(Vs + j * LDT + tx * 4);
            float vr[4] = {vv.x, vv.y, vv.z, vv.w};
            #pragma unroll
            for (int i = 0; i < 4; i++)
                #pragma unroll
                for (int dd = 0; dd < 4; dd++)
                    acc[i][dd] = fmaf(pv[i], vr[dd], acc[i][dd]);
        }
    }
    __syncthreads();

    #pragma unroll
    for (int i = 0; i < 4; i++) {
        float linv = 1.f / lrow[ty * 4 + i];
        __nv_bfloat162 p0 = __floats2bfloat162_rn(acc[i][0] * linv, acc[i][1] * linv);
        __nv_bfloat162 p1 = __floats2bfloat162_rn(acc[i][2] * linv, acc[i][3] * linv);
        uint2 u;
        u.x = *reinterpret_cast<uint32_t*>(&p0);
        u.y = *reinterpret_cast<uint32_t*>(&p1);
        *reinterpret_cast<uint2*>(O + ((long)(b * NQ + qt * TQ + ty * 4 + i)) * DIM
                                    + h * DH + tx * 4) = u;
    }
}

// ---------------- launch ----------------
extern "C" void kernel_launch(void* const* d_in, const int* in_sizes, int n_in,
                              void* d_out, int out_size)
{
    const float* query   = (const float*)d_in[0];
    const float* kv      = (const float*)d_in[1];
    const float* ln_q_g  = (const float*)d_in[2];
    const float* ln_q_b  = (const float*)d_in[3];
    const float* ln_kv_g = (const float*)d_in[4];
    const float* ln_kv_b = (const float*)d_in[5];
    const float* Wq = (const float*)d_in[6];
    const float* bq = (const float*)d_in[7];
    const float* Wk = (const float*)d_in[8];
    const float* bk = (const float*)d_in[9];
    const float* Wv = (const float*)d_in[10];
    const float* bv = (const float*)d_in[11];
    const float* Wo = (const float*)d_in[12];
    const float* bo = (const float*)d_in[13];
    float* out = (float*)d_out;

    __nv_bfloat16 *kvn, *wt, *ab;
    float *qb, *kb, *vb;
    cudaGetSymbolAddress((void**)&kvn, g_kvn);
    cudaGetSymbolAddress((void**)&wt,  g_wt);
    cudaGetSymbolAddress((void**)&qb,  g_q);
    cudaGetSymbolAddress((void**)&kb,  g_k);
    cudaGetSymbolAddress((void**)&vb,  g_v);
    cudaGetSymbolAddress((void**)&ab,  g_att);

    cudaFuncSetAttribute(gemm_bf16_kernel, cudaFuncAttributeMaxDynamicSharedMemorySize, GEMM_SMEM);
    cudaFuncSetAttribute(attn_kernel, cudaFuncAttributeMaxDynamicSharedMemorySize, ATTN_SMEM);

    // transpose+convert weights to bf16 [N][K]
    {
        dim3 grid(DIM / 32, DIM / 32), blk(32, 8);
        wtrans_kernel<<<grid, blk>>>(Wq, wt + 0L * DIM * DIM);
        wtrans_kernel<<<grid, blk>>>(Wk, wt + 1L * DIM * DIM);
        wtrans_kernel<<<grid, blk>>>(Wv, wt + 2L * DIM * DIM);
        wtrans_kernel<<<grid, blk>>>(Wo, wt + 3L * DIM * DIM);
    }

    // LayerNorms -> bf16 (kv rows [0,2048), q rows [2048,2560) per batch)
    ln_kernel<<<BATCH * NKV, 256>>>(kv,    kvn, ln_kv_g, ln_kv_b, NKV, NCTX, 0);
    ln_kernel<<<BATCH * NQ,  256>>>(query, kvn, ln_q_g,  ln_q_b,  NQ,  NCTX, NKV);

    // Q = q_n @ Wq + bq  (per-batch strided A)
    {
        dim3 grid(DIM / 128, NQ / 128, BATCH);
        gemm_bf16_kernel<<<grid, 256, GEMM_SMEM>>>(
            kvn + (long)NKV * DIM, wt + 0L * DIM * DIM, bq, nullptr, qb,
            (long)NCTX * DIM, (long)NQ * DIM);
    }
    // K, V (flat M = 10240)
    {
        dim3 grid(DIM / 128, BATCH * NCTX / 128, 1);
        gemm_bf16_kernel<<<grid, 256, GEMM_SMEM>>>(kvn, wt + 1L * DIM * DIM, bk, nullptr, kb, 0, 0);
        gemm_bf16_kernel<<<grid, 256, GEMM_SMEM>>>(kvn, wt + 2L * DIM * DIM, bv, nullptr, vb, 0, 0);
    }

    // attention (fp32 in, bf16 out)
    {
        dim3 grid(NQ / TQ, HEADS, BATCH);
        attn_kernel<<<grid, 256, ATTN_SMEM>>>(qb, kb, vb, ab);
    }

    // out = attn @ Wo + bo + residual(query)  (flat M = 2048)
    {
        dim3 grid(DIM / 128, BATCH * NQ / 128, 1);
        gemm_bf16_kernel<<<grid, 256, GEMM_SMEM>>>(ab, wt + 3L * DIM * DIM, bo, query, out, 0, 0);
    }
}

// round 4
// speedup vs baseline: 6.1034x; 2.7188x over previous
#include <cuda_runtime.h>
#include <cuda_bf16.h>
#include <cstdint>

#define DIM   1024
#define NQ    512
#define NKV   2048
#define NCTX  2560
#define BATCH 4
#define HEADS 16
#define DH    64

// ---------------- scratch (no allocs allowed) ----------------
__device__ __nv_bfloat16 g_kvn[(long)BATCH * NCTX * DIM];  // LN outputs (bf16)
__device__ __nv_bfloat16 g_wt [4L * DIM * DIM];            // transposed bf16 weights [n][k]
__device__ __nv_bfloat16 g_q  [(long)BATCH * NQ   * DIM];
__device__ __nv_bfloat16 g_k  [(long)BATCH * NCTX * DIM];
__device__ __nv_bfloat16 g_v  [(long)BATCH * NCTX * DIM];
__device__ __nv_bfloat16 g_att[(long)BATCH * NQ   * DIM];  // attention output (bf16)

// ================= PTX helpers (base sm_103 features only) =================
__device__ __forceinline__ uint32_t smem_u32(const void* p) {
    uint32_t a;
    asm("{ .reg .u64 t; cvta.to.shared.u64 t, %1; cvt.u32.u64 %0, t; }" : "=r"(a) : "l"(p));
    return a;
}
__device__ __forceinline__ void cp16(uint32_t dst, const void* src) {
    asm volatile("cp.async.cg.shared.global [%0], [%1], 16;" :: "r"(dst), "l"(src));
}
__device__ __forceinline__ void cp_commit() {
    asm volatile("cp.async.commit_group;" ::: "memory");
}
template <int N>
__device__ __forceinline__ void cp_wait() {
    asm volatile("cp.async.wait_group %0;" :: "n"(N) : "memory");
}
#define LDSM_X4(r0, r1, r2, r3, addr) \
    asm volatile("ldmatrix.sync.aligned.m8n8.x4.shared.b16 {%0,%1,%2,%3}, [%4];" \
        : "=r"(r0), "=r"(r1), "=r"(r2), "=r"(r3) : "r"(addr))
#define LDSM_X4_T(r0, r1, r2, r3, addr) \
    asm volatile("ldmatrix.sync.aligned.m8n8.x4.trans.shared.b16 {%0,%1,%2,%3}, [%4];" \
        : "=r"(r0), "=r"(r1), "=r"(r2), "=r"(r3) : "r"(addr))
#define MMA16816(d, a0, a1, a2, a3, b0, b1) \
    asm volatile("mma.sync.aligned.m16n8k16.row.col.f32.bf16.bf16.f32 " \
        "{%0,%1,%2,%3}, {%4,%5,%6,%7}, {%8,%9}, {%0,%1,%2,%3};" \
        : "+f"((d)[0]), "+f"((d)[1]), "+f"((d)[2]), "+f"((d)[3]) \
        : "r"(a0), "r"(a1), "r"(a2), "r"(a3), "r"(b0), "r"(b1))

__device__ __forceinline__ uint32_t pack_bf16(float x, float y) {
    __nv_bfloat162 p = __floats2bfloat162_rn(x, y);
    return *reinterpret_cast<uint32_t*>(&p);
}

// ---------------- LayerNorm (fp32 in, bf16 out) ----------------
__global__ __launch_bounds__(256)
void ln_kernel(const float* __restrict__ x, __nv_bfloat16* __restrict__ y,
               const float* __restrict__ g, const float* __restrict__ bb,
               int rows_per_batch, int out_batch_stride, int out_row_off)
{
    __shared__ float red[8];
    __shared__ float s_mu, s_rstd;
    long row = blockIdx.x;
    int b = (int)(row / rows_per_batch);
    int r = (int)(row - (long)b * rows_per_batch);
    const float* xr = x + row * (long)DIM;
    __nv_bfloat16* yr = y + ((long)b * out_batch_stride + out_row_off + r) * (long)DIM;
    int tid = threadIdx.x;

    float4 v = *(const float4*)(xr + tid * 4);
    float s = v.x + v.y + v.z + v.w;
    #pragma unroll
    for (int o = 16; o > 0; o >>= 1) s += __shfl_xor_sync(0xffffffffu, s, o);
    if ((tid & 31) == 0) red[tid >> 5] = s;
    __syncthreads();
    if (tid == 0) {
        float t = 0.f;
        #pragma unroll
        for (int i = 0; i < 8; i++) t += red[i];
        s_mu = t * (1.f / DIM);
    }
    __syncthreads();
    float mu = s_mu;
    float d0 = v.x - mu, d1 = v.y - mu, d2 = v.z - mu, d3 = v.w - mu;
    float q = d0*d0 + d1*d1 + d2*d2 + d3*d3;
    #pragma unroll
    for (int o = 16; o > 0; o >>= 1) q += __shfl_xor_sync(0xffffffffu, q, o);
    if ((tid & 31) == 0) red[tid >> 5] = q;
    __syncthreads();
    if (tid == 0) {
        float t = 0.f;
        #pragma unroll
        for (int i = 0; i < 8; i++) t += red[i];
        s_rstd = rsqrtf(t * (1.f / DIM) + 1e-5f);
    }
    __syncthreads();
    float rstd = s_rstd;
    float4 gg = *(const float4*)(g  + tid * 4);
    float4 b4 = *(const float4*)(bb + tid * 4);
    float o0 = d0 * rstd * gg.x + b4.x;
    float o1 = d1 * rstd * gg.y + b4.y;
    float o2 = d2 * rstd * gg.z + b4.z;
    float o3 = d3 * rstd * gg.w + b4.w;
    uint2 u;
    u.x = pack_bf16(o0, o1);
    u.y = pack_bf16(o2, o3);
    *reinterpret_cast<uint2*>(yr + tid * 4) = u;
}

// ---------------- weight transpose+convert: Wt[n][k] = bf16(W[k][n]) ----------------
__global__ __launch_bounds__(256)
void wtrans_kernel(const float* __restrict__ W, __nv_bfloat16* __restrict__ Wt)
{
    __shared__ float s[32][33];
    int tx = threadIdx.x, ty = threadIdx.y;
    int n0 = blockIdx.x * 32, k0 = blockIdx.y * 32;
    #pragma unroll
    for (int i = 0; i < 32; i += 8)
        s[ty + i][tx] = W[(long)(k0 + ty + i) * DIM + n0 + tx];
    __syncthreads();
    #pragma unroll
    for (int i = 0; i < 32; i += 8)
        Wt[(long)(n0 + ty + i) * DIM + k0 + tx] = __float2bfloat16(s[tx][ty + i]);
}

// ---------------- mma.sync bf16 GEMM ----------------
// 128x128 tile, BK=32, 256 threads (8 warps: 2M x 4N), 3-stage cp.async
// BF16OUT: write bf16 (no resid). else: write f32 with optional resid.
#define GK        1024
#define NIT       32
#define ST        3
#define STAGE_B   16384
#define GEMM_SMEM (ST * STAGE_B + 1024)

template <bool BF16OUT>
__global__ __launch_bounds__(256)
void gemm_bf16_kernel(const __nv_bfloat16* __restrict__ A,
                      const __nv_bfloat16* __restrict__ Bt,
                      const float* __restrict__ bias,
                      const float* __restrict__ resid,
                      void* __restrict__ Cv,
                      long strideA, long strideC)
{
    extern __shared__ char smraw[];
    uint32_t base = (smem_u32(smraw) + 1023u) & ~1023u;

    const int tid  = threadIdx.x;
    const int lane = tid & 31;
    const int wid  = tid >> 5;
    const int wm   = wid & 1;
    const int wn   = wid >> 1;

    const __nv_bfloat16* Ab = A + blockIdx.z * strideA + (long)blockIdx.y * 128 * GK;
    const __nv_bfloat16* Bb = Bt + (long)blockIdx.x * 128 * GK;

    const int lr  = tid >> 1;
    const int lcb = (tid & 1) * 2;
    const int lsw = (lr >> 1) & 3;
    const uint32_t lrowoff = lr * 64;

    auto load_stage = [&](int it) {
        uint32_t sA = base + (it % ST) * STAGE_B;
        uint32_t sB = sA + 8192;
        const __nv_bfloat16* ga = Ab + (long)lr * GK + it * 32 + lcb * 8;
        const __nv_bfloat16* gb = Bb + (long)lr * GK + it * 32 + lcb * 8;
        uint32_t o0 = lrowoff + (uint32_t)((lcb ^ lsw) << 4);
        uint32_t o1 = lrowoff + (uint32_t)(((lcb + 1) ^ lsw) << 4);
        cp16(sA + o0, ga);
        cp16(sA + o1, ga + 8);
        cp16(sB + o0, gb);
        cp16(sB + o1, gb + 8);
        cp_commit();
    };

    float acc[4][4][4];
    #pragma unroll
    for (int i = 0; i < 4; i++)
        #pragma unroll
        for (int j = 0; j < 4; j++)
            #pragma unroll
            for (int q = 0; q < 4; q++) acc[i][j][q] = 0.f;

    load_stage(0);
    load_stage(1);

    const int a_r8 = (lane & 7) + ((lane >> 3) & 1) * 8;
    const int a_cq = (lane >> 4);
    const int b_r8 = (lane & 7) + ((lane >> 4) & 1) * 8;
    const int b_cq = (lane >> 3) & 1;

    for (int it = 0; it < NIT; it++) {
        cp_wait<1>();
        __syncthreads();
        if (it + 2 < NIT) load_stage(it + 2);
        else cp_commit();

        uint32_t sA = base + (it % ST) * STAGE_B;
        uint32_t sB = sA + 8192;

        #pragma unroll
        for (int ks = 0; ks < 2; ks++) {
            uint32_t a[4][4];
            #pragma unroll
            for (int i = 0; i < 4; i++) {
                int r = wm * 64 + i * 16 + a_r8;
                int c = ks * 2 + a_cq;
                LDSM_X4(a[i][0], a[i][1], a[i][2], a[i][3],
                        sA + r * 64 + (((c ^ ((r >> 1) & 3))) << 4));
            }
            uint32_t b[2][4];
            #pragma unroll
            for (int jj = 0; jj < 2; jj++) {
                int r = wn * 32 + jj * 16 + b_r8;
                int c = ks * 2 + b_cq;
                LDSM_X4(b[jj][0], b[jj][1], b[jj][2], b[jj][3],
                        sB + r * 64 + (((c ^ ((r >> 1) & 3))) << 4));
            }
            #pragma unroll
            for (int i = 0; i < 4; i++)
                #pragma unroll
                for (int j = 0; j < 4; j++)
                    MMA16816(acc[i][j], a[i][0], a[i][1], a[i][2], a[i][3],
                             b[j >> 1][(j & 1) * 2], b[j >> 1][(j & 1) * 2 + 1]);
        }
    }

    const long rowbase = blockIdx.z * strideC + ((long)blockIdx.y * 128 + wm * 64) * (long)DIM;
    const int  col0    = blockIdx.x * 128 + wn * 32;
    #pragma unroll
    for (int i = 0; i < 4; i++) {
        int rr = i * 16 + (lane >> 2);
        #pragma unroll
        for (int j = 0; j < 4; j++) {
            int cc = col0 + j * 8 + (lane & 3) * 2;
            float bx = bias[cc], by = bias[cc + 1];
            long off0 = rowbase + (long)rr * DIM + cc;
            long off1 = off0 + 8L * DIM;
            if (BF16OUT) {
                __nv_bfloat16* Cb = (__nv_bfloat16*)Cv;
                *(uint32_t*)(Cb + off0) = pack_bf16(acc[i][j][0] + bx, acc[i][j][1] + by);
                *(uint32_t*)(Cb + off1) = pack_bf16(acc[i][j][2] + bx, acc[i][j][3] + by);
            } else {
                float* Cf = (float*)Cv;
                float2 o0, o1;
                o0.x = acc[i][j][0] + bx; o0.y = acc[i][j][1] + by;
                o1.x = acc[i][j][2] + bx; o1.y = acc[i][j][3] + by;
                if (resid) {
                    float2 r0 = *(const float2*)(resid + off0);
                    float2 r1 = *(const float2*)(resid + off1);
                    o0.x += r0.x; o0.y += r0.y;
                    o1.x += r1.x; o1.y += r1.y;
                }
                *(float2*)(Cf + off0) = o0;
                *(float2*)(Cf + off1) = o1;
            }
        }
    }
}

// ---------------- Tensor-core flash attention ----------------
// 64 q-rows per CTA (4 warps x 16 rows), 64-key tiles, double-buffered cp.async K/V.
// Smem rows 128B (64 bf16), swizzle: chunk c ^ (row & 7).
#define NT_KV      (NCTX / 64)          // 40
#define ATTN_SMEM  (8192 + 2 * 16384)   // Q + 2 stages (K 8KB + V 8KB)

__global__ __launch_bounds__(128)
void fattn_kernel(const __nv_bfloat16* __restrict__ Q,
                  const __nv_bfloat16* __restrict__ K,
                  const __nv_bfloat16* __restrict__ V,
                  __nv_bfloat16* __restrict__ O)
{
    extern __shared__ char smraw[];
    uint32_t base = (smem_u32(smraw) + 127u) & ~127u;
    uint32_t sQ  = base;
    uint32_t sKV = base + 8192;     // stage s: K at sKV + s*16384, V at +8192

    const int tid  = threadIdx.x;
    const int lane = tid & 31;
    const int wq   = tid >> 5;
    const int qt = blockIdx.x, h = blockIdx.y, b = blockIdx.z;

    const __nv_bfloat16* Qg = Q + ((long)(b * NQ + qt * 64)) * DIM + h * DH;
    const __nv_bfloat16* Kg = K + (long)b * NCTX * DIM + h * DH;
    const __nv_bfloat16* Vg = V + (long)b * NCTX * DIM + h * DH;

    const int lr = tid >> 1;           // row 0..63
    const int lc = (tid & 1) * 4;      // 4 chunks of 16B

    // prologue loads: group0 = Q + KV(0), group1 = KV(1)
    {
        const __nv_bfloat16* src = Qg + (long)lr * DIM + lc * 8;
        #pragma unroll
        for (int c = 0; c < 4; c++)
            cp16(sQ + lr * 128 + (((lc + c) ^ (lr & 7)) << 4), src + c * 8);
    }
    auto load_kv = [&](int t) {
        uint32_t sK = sKV + (t & 1) * 16384;
        const __nv_bfloat16* ks = Kg + (long)(t * 64 + lr) * DIM + lc * 8;
        const __nv_bfloat16* vs = Vg + (long)(t * 64 + lr) * DIM + lc * 8;
        #pragma unroll
        for (int c = 0; c < 4; c++) {
            uint32_t sw = ((lc + c) ^ (lr & 7)) << 4;
            cp16(sK + lr * 128 + sw, ks + c * 8);
            cp16(sK + 8192 + lr * 128 + sw, vs + c * 8);
        }
    };
    load_kv(0);
    cp_commit();
    load_kv(1);
    cp_commit();
    cp_wait<1>();     // Q + KV(0) ready
    __syncthreads();

    // Q fragments (held in registers for all 40 tiles)
    uint32_t aq[4][4];
    {
        int r = wq * 16 + (lane & 7) + ((lane >> 3) & 1) * 8;
        #pragma unroll
        for (int ks = 0; ks < 4; ks++) {
            int c = ks * 2 + (lane >> 4);
            LDSM_X4(aq[ks][0], aq[ks][1], aq[ks][2], aq[ks][3],
                    sQ + r * 128 + ((c ^ (r & 7)) << 4));
        }
    }

    const float C = 0.125f * 1.44269504f;   // scale * log2(e)
    float m0 = -1e30f, m1 = -1e30f, l0 = 0.f, l1 = 0.f;
    float o[8][4];
    #pragma unroll
    for (int nt = 0; nt < 8; nt++)
        #pragma unroll
        for (int q = 0; q < 4; q++) o[nt][q] = 0.f;

    const int r_ab = (lane & 7) + ((lane >> 3) & 1) * 8;   // A/V-trans row pattern
    const int r_b  = (lane & 7) + ((lane >> 4) & 1) * 8;   // K (non-trans B) row pattern
    const int cq_a = lane >> 4;
    const int cq_b = (lane >> 3) & 1;

    for (int t = 0; t < NT_KV; t++) {
        uint32_t sK = sKV + (t & 1) * 16384;
        uint32_t sV = sK + 8192;

        // ---- S = Q @ K^T ----
        float st[8][4];
        #pragma unroll
        for (int nt = 0; nt < 8; nt++)
            #pragma unroll
            for (int q = 0; q < 4; q++) st[nt][q] = 0.f;

        #pragma unroll
        for (int ks = 0; ks < 4; ks++) {
            #pragma unroll
            for (int kg = 0; kg < 4; kg++) {
                int r = kg * 16 + r_b;
                int c = ks * 2 + cq_b;
                uint32_t b0, b1, b2, b3;
                LDSM_X4(b0, b1, b2, b3, sK + r * 128 + ((c ^ (r & 7)) << 4));
                MMA16816(st[2 * kg],     aq[ks][0], aq[ks][1], aq[ks][2], aq[ks][3], b0, b1);
                MMA16816(st[2 * kg + 1], aq[ks][0], aq[ks][1], aq[ks][2], aq[ks][3], b2, b3);
            }
        }

        // ---- online softmax (log2 domain) ----
        float mx0 = -1e30f, mx1 = -1e30f;
        #pragma unroll
        for (int nt = 0; nt < 8; nt++) {
            mx0 = fmaxf(mx0, fmaxf(st[nt][0], st[nt][1]));
            mx1 = fmaxf(mx1, fmaxf(st[nt][2], st[nt][3]));
        }
        mx0 = fmaxf(mx0, __shfl_xor_sync(0xffffffffu, mx0, 1));
        mx0 = fmaxf(mx0, __shfl_xor_sync(0xffffffffu, mx0, 2));
        mx1 = fmaxf(mx1, __shfl_xor_sync(0xffffffffu, mx1, 1));
        mx1 = fmaxf(mx1, __shfl_xor_sync(0xffffffffu, mx1, 2));
        float nm0 = fmaxf(m0, mx0 * C);
        float nm1 = fmaxf(m1, mx1 * C);
        float al0 = exp2f(m0 - nm0);
        float al1 = exp2f(m1 - nm1);
        m0 = nm0; m1 = nm1;

        float s0 = 0.f, s1 = 0.f;
        uint32_t pa[4][4];
        #pragma unroll
        for (int nt = 0; nt < 8; nt++) {
            float p0 = exp2f(st[nt][0] * C - nm0);
            float p1 = exp2f(st[nt][1] * C - nm0);
            float p2 = exp2f(st[nt][2] * C - nm1);
            float p3 = exp2f(st[nt][3] * C - nm1);
            s0 += p0 + p1;
            s1 += p2 + p3;
            pa[nt >> 1][(nt & 1) * 2 + 0] = pack_bf16(p0, p1);
            pa[nt >> 1][(nt & 1) * 2 + 1] = pack_bf16(p2, p3);
        }
        s0 += __shfl_xor_sync(0xffffffffu, s0, 1);
        s0 += __shfl_xor_sync(0xffffffffu, s0, 2);
        s1 += __shfl_xor_sync(0xffffffffu, s1, 1);
        s1 += __shfl_xor_sync(0xffffffffu, s1, 2);
        l0 = l0 * al0 + s0;
        l1 = l1 * al1 + s1;
        #pragma unroll
        for (int nt = 0; nt < 8; nt++) {
            o[nt][0] *= al0; o[nt][1] *= al0;
            o[nt][2] *= al1; o[nt][3] *= al1;
        }

        // ---- O += P @ V ----
        #pragma unroll
        for (int kt = 0; kt < 4; kt++) {
            #pragma unroll
            for (int np = 0; np < 4; np++) {
                int r = kt * 16 + r_ab;
                int c = np * 2 + cq_a;
                uint32_t b0, b1, b2, b3;
                LDSM_X4_T(b0, b1, b2, b3, sV + r * 128 + ((c ^ (r & 7)) << 4));
                MMA16816(o[2 * np],     pa[kt][0], pa[kt][1], pa[kt][2], pa[kt][3], b0, b1);
                MMA16816(o[2 * np + 1], pa[kt][0], pa[kt][1], pa[kt][2], pa[kt][3], b2, b3);
            }
        }

        __syncthreads();
        if (t + 2 < NT_KV) load_kv(t + 2);
        cp_commit();
        cp_wait<1>();
        __syncthreads();
    }

    // ---- write O (bf16) ----
    float li0 = 1.f / l0, li1 = 1.f / l1;
    int row = qt * 64 + wq * 16 + (lane >> 2);
    __nv_bfloat16* Og = O + ((long)(b * NQ + row)) * DIM + h * DH + (lane & 3) * 2;
    #pragma unroll
    for (int nt = 0; nt < 8; nt++) {
        *(uint32_t*)(Og + nt * 8)            = pack_bf16(o[nt][0] * li0, o[nt][1] * li0);
        *(uint32_t*)(Og + 8L * DIM + nt * 8) = pack_bf16(o[nt][2] * li1, o[nt][3] * li1);
    }
}

// ---------------- launch ----------------
extern "C" void kernel_launch(void* const* d_in, const int* in_sizes, int n_in,
                              void* d_out, int out_size)
{
    const float* query   = (const float*)d_in[0];
    const float* kv      = (const float*)d_in[1];
    const float* ln_q_g  = (const float*)d_in[2];
    const float* ln_q_b  = (const float*)d_in[3];
    const float* ln_kv_g = (const float*)d_in[4];
    const float* ln_kv_b = (const float*)d_in[5];
    const float* Wq = (const float*)d_in[6];
    const float* bq = (const float*)d_in[7];
    const float* Wk = (const float*)d_in[8];
    const float* bk = (const float*)d_in[9];
    const float* Wv = (const float*)d_in[10];
    const float* bv = (const float*)d_in[11];
    const float* Wo = (const float*)d_in[12];
    const float* bo = (const float*)d_in[13];
    float* out = (float*)d_out;

    __nv_bfloat16 *kvn, *wt, *qb, *kb, *vb, *ab;
    cudaGetSymbolAddress((void**)&kvn, g_kvn);
    cudaGetSymbolAddress((void**)&wt,  g_wt);
    cudaGetSymbolAddress((void**)&qb,  g_q);
    cudaGetSymbolAddress((void**)&kb,  g_k);
    cudaGetSymbolAddress((void**)&vb,  g_v);
    cudaGetSymbolAddress((void**)&ab,  g_att);

    cudaFuncSetAttribute(gemm_bf16_kernel<true>,
                         cudaFuncAttributeMaxDynamicSharedMemorySize, GEMM_SMEM);
    cudaFuncSetAttribute(gemm_bf16_kernel<false>,
                         cudaFuncAttributeMaxDynamicSharedMemorySize, GEMM_SMEM);
    cudaFuncSetAttribute(fattn_kernel,
                         cudaFuncAttributeMaxDynamicSharedMemorySize, ATTN_SMEM);

    // transpose+convert weights to bf16 [N][K]
    {
        dim3 grid(DIM / 32, DIM / 32), blk(32, 8);
        wtrans_kernel<<<grid, blk>>>(Wq, wt + 0L * DIM * DIM);
        wtrans_kernel<<<grid, blk>>>(Wk, wt + 1L * DIM * DIM);
        wtrans_kernel<<<grid, blk>>>(Wv, wt + 2L * DIM * DIM);
        wtrans_kernel<<<grid, blk>>>(Wo, wt + 3L * DIM * DIM);
    }

    // LayerNorms -> bf16 (kv rows [0,2048), q rows [2048,2560) per batch)
    ln_kernel<<<BATCH * NKV, 256>>>(kv,    kvn, ln_kv_g, ln_kv_b, NKV, NCTX, 0);
    ln_kernel<<<BATCH * NQ,  256>>>(query, kvn, ln_q_g,  ln_q_b,  NQ,  NCTX, NKV);

    // Q = q_n @ Wq + bq  (bf16 out, per-batch strided A)
    {
        dim3 grid(DIM / 128, NQ / 128, BATCH);
        gemm_bf16_kernel<true><<<grid, 256, GEMM_SMEM>>>(
            kvn + (long)NKV * DIM, wt + 0L * DIM * DIM, bq, nullptr, qb,
            (long)NCTX * DIM, (long)NQ * DIM);
    }
    // K, V (bf16 out, flat M = 10240)
    {
        dim3 grid(DIM / 128, BATCH * NCTX / 128, 1);
        gemm_bf16_kernel<true><<<grid, 256, GEMM_SMEM>>>(
            kvn, wt + 1L * DIM * DIM, bk, nullptr, kb, 0, 0);
        gemm_bf16_kernel<true><<<grid, 256, GEMM_SMEM>>>(
            kvn, wt + 2L * DIM * DIM, bv, nullptr, vb, 0, 0);
    }

    // tensor-core flash attention (bf16 in/out)
    {
        dim3 grid(NQ / 64, HEADS, BATCH);
        fattn_kernel<<<grid, 128, ATTN_SMEM>>>(qb, kb, vb, ab);
    }

    // out = attn @ Wo + bo + residual(query)  (f32 out, flat M = 2048)
    {
        dim3 grid(DIM / 128, BATCH * NQ / 128, 1);
        gemm_bf16_kernel<false><<<grid, 256, GEMM_SMEM>>>(
            ab, wt + 3L * DIM * DIM, bo, query, out, 0, 0);
    }
}